// round 8
// baseline (speedup 1.0000x reference)
#include <cuda_runtime.h>
#include <math.h>

// ---------------- constants (from reference) ----------------
#define SPIN_LEN   100
#define TRAIN_LEN  200000
#define ML_C       2.9086f
#define SL_C       1.898f
#define L2E        1.4426950408889634f

#define CH      8                    // output steps per chain (8 = affine-addr trick)
#define WARM    96                   // discarded convergence steps (multiple of 8)
#define OUTW    (64 * CH)            // 512 output steps per warp (2 chains/thread)
#define NW      (WARM + OUTW)        // 608-step input window per warp
#define NBLK    512                  // B / OUTW
#define SK4(g)  ((g) + ((g) >> 3))   // float4 skew: conflict-free LDS.128 at stride 8
#define SWIN4   (SK4(NW - 1) + 1)    // 683
#define SKO(t)  ((t) + ((t) >> 5))   // float skew for output transpose buffer
#define SOUT    (SKO(OUTW - 1) + 1)  // 527

#define STD_N      (TRAIN_LEN - SPIN_LEN)          // 199900
#define STD_CHUNK  ((STD_N + NBLK - 1) / NBLK)     // 391

// ---------------- device scratch (statically zero-initialized) ----------------
__device__ double   g_ps[NBLK];
__device__ double   g_pq[NBLK];
__device__ unsigned g_tick;
__device__ int      g_flag;
__device__ float    g_obsstd;

__device__ __forceinline__ float ex2f(float x) { float y; asm("ex2.approx.f32 %0, %1;" : "=f"(y) : "f"(x)); return y; }
__device__ __forceinline__ float rcpf(float x) { float y; asm("rcp.approx.f32 %0, %1;" : "=f"(y) : "f"(x)); return y; }

// reset inter-block sync state (runs before the fused kernel each replay)
__global__ void k_init() { g_tick = 0; g_flag = 0; }

// ---------------- fused kernel ----------------
// 512 one-warp blocks, all co-resident (32KB smem, 32 threads -> >=6 blocks/SM).
// Phase A: stage this warp's 608-step input window (+ precomputed ol(u2)).
// Phase B: distributed std(y_obs[100:200000]) - last block finalizes, sets flag.
// Phase C: warmup (2 interleaved chains/thread, divide-free) + 8 output steps.
// Phase D: flush streams 0-9; spin on flag (set ~immediately); flush std streams.
__global__ void __launch_bounds__(32)
k_fused(const float* __restrict__ x, const float* __restrict__ y,
        float* __restrict__ out, int B,
        const float* cmean, const float* cstd,
        const float* W_rom, const float* W_rlm, const float* W_rfm,
        const float* b0_yom, const float* W_b1_yom,
        const float* b0_ylm, const float* W_b2_ylm,
        const float* theltaC)
{
    __shared__ float4 sw[SWIN4];
    __shared__ float  ob[10 * SOUT];

    const int lane   = threadIdx.x;
    const int bid    = blockIdx.x;
    const int base   = bid * OUTW;          // first emitted global step
    const int wstart = base - WARM;         // window start (may be < 0)

    // ---- derived scalar params (cheap, redundant per block) ----
    const float eo  = expf(W_rom[0]);
    const float el  = expf(W_rlm[0]);
    const float den = eo + el + expf(W_rfm[0]);
    const float thr = expf(theltaC[0]);
    const float oo1 = eo / den;
    const float ol1 = el / den;
    const float a1  = W_b1_yom[0] / cstd[0];
    const float a1n = -a1 * L2E;
    const float k01n = -(b0_yom[0] - cmean[0] * a1) * L2E;
    const float a2  = W_b2_ylm[0] / SL_C;
    const float a2n = -a2 * L2E;
    const float k02n = -(b0_ylm[0] - ML_C * a2) * L2E;

    // ---- Phase A: stage window (coalesced) + precompute ol(u2) ----
    // Zero-fill for steps < 0 keeps c == 0 exactly (m=min(0,thr)=0, olcc=0, ooc=0).
    #pragma unroll
    for (int g = lane; g < NW; g += 32) {
        int i = wstart + g;
        float u1 = 0.0f, u2 = 0.0f, ol = 0.0f;
        if (i >= 0) {
            float2 v = reinterpret_cast<const float2*>(x)[i];
            u1 = v.x; u2 = v.y;
            ol = ol1 * rcpf(1.0f + ex2f(fmaf(u2, a2n, k02n)));
        }
        sw[SK4(g)] = make_float4(u1, u2, ol, 0.0f);
    }

    // ---- Phase B: std slice ----
    {
        int s0 = SPIN_LEN + bid * STD_CHUNK;
        int s1 = min(s0 + STD_CHUNK, TRAIN_LEN);
        float a = 0.0f, b = 0.0f;
        for (int i = s0 + lane; i < s1; i += 32) {
            float v = y[i];
            a += v; b = fmaf(v, v, b);
        }
        #pragma unroll
        for (int o = 16; o > 0; o >>= 1) {
            a += __shfl_down_sync(0xffffffffu, a, o);
            b += __shfl_down_sync(0xffffffffu, b, o);
        }
        int last = 0;
        if (lane == 0) {
            g_ps[bid] = (double)a;
            g_pq[bid] = (double)b;
            __threadfence();
            last = (atomicAdd(&g_tick, 1u) == NBLK - 1);
        }
        if (__shfl_sync(0xffffffffu, last, 0)) {
            // fixed-order (deterministic) final reduction over 512 partials
            double sa = 0.0, sb = 0.0;
            for (int i = lane; i < NBLK; i += 32) { sa += g_ps[i]; sb += g_pq[i]; }
            #pragma unroll
            for (int o = 16; o > 0; o >>= 1) {
                sa += __shfl_down_sync(0xffffffffu, sa, o);
                sb += __shfl_down_sync(0xffffffffu, sb, o);
            }
            if (lane == 0) {
                double n = (double)STD_N;
                double mean = sa / n;
                double var  = (sb - sa * mean) / (n - 1.0);
                g_obsstd = (float)sqrt(var);
                __threadfence();
                atomicExch(&g_flag, 1);
            }
        }
    }
    __syncwarp();

    const int g0 = lane * CH;           // chain 0 window start (multiple of 8)
    const int g1 = (lane + 32) * CH;    // chain 1 window start
    float c0 = 0.0f, c1 = 0.0f;

    // ---- Phase C1: warmup, divide-free, affine smem addressing ----
    // step: m = min(u1, thr-c); olcc = min(ol*c, u2); c' = fma(-oo1*c, s, (c-olcc)+m)
    for (int k0 = 0; k0 < WARM; k0 += 8) {
        const float4* p0 = &sw[SK4(g0 + k0)];   // (g+k)>>3 constant over k in [0,8)
        const float4* p1 = &sw[SK4(g1 + k0)];
        #pragma unroll
        for (int k = 0; k < 8; ++k) {
            {
                float4 v = p0[k];
                float s    = rcpf(1.0f + ex2f(fmaf(c0, a1n, k01n)));
                float t    = oo1 * c0;
                float olcc = fminf(v.z * c0, v.y);
                float m    = fminf(v.x, thr - c0);
                c0 = fmaf(-t, s, (c0 - olcc) + m);
            }
            {
                float4 v = p1[k];
                float s    = rcpf(1.0f + ex2f(fmaf(c1, a1n, k01n)));
                float t    = oo1 * c1;
                float olcc = fminf(v.z * c1, v.y);
                float m    = fminf(v.x, thr - c1);
                c1 = fmaf(-t, s, (c1 - olcc) + m);
            }
        }
    }

    // ---- Phase C2: 8 output steps per chain into smem transpose buffer ----
    const int sb0 = 8 * lane + (lane >> 2);                // SKO(8*lane)
    const int sb1 = 8 * (lane + 32) + ((lane + 32) >> 2);  // SKO(8*(lane+32))
    {
        const float4* p0 = &sw[SK4(g0 + WARM)];
        const float4* p1 = &sw[SK4(g1 + WARM)];
        #pragma unroll
        for (int k = 0; k < CH; ++k) {
            #pragma unroll
            for (int j = 0; j < 2; ++j) {
                float  c = j ? c1 : c0;
                float4 v = j ? p1[k] : p0[k];
                float* q = &ob[(j ? sb1 : sb0) + k];

                float s    = rcpf(1.0f + ex2f(fmaf(c, a1n, k01n)));
                float oo   = oo1 * s;
                float ooc  = oo * c;
                float olc  = (c > 0.0f) ? fminf(v.z, v.y * rcpf(c)) : v.z;
                float olcc = olc * c;
                float px   = fmaxf(v.x + c - thr, 0.0f);
                float ib   = (v.x > 0.0f) ? px * rcpf(v.x) : 0.0f;
                float f    = (1.0f - oo) - olc;

                q[0 * SOUT] = ooc + px;   // h_n
                q[1 * SOUT] = c;          // c_n (pre-update)
                q[2 * SOUT] = v.z * c;    // l_n
                q[3 * SOUT] = olcc;       // lc_n
                q[4 * SOUT] = px;         // bp_n
                q[5 * SOUT] = ib;         // g_ib
                q[6 * SOUT] = oo;         // g_oo
                q[7 * SOUT] = v.z;        // g_ol
                q[8 * SOUT] = olc;        // g_olc
                q[9 * SOUT] = f;          // g_f

                c = ((c - ooc) - olcc) + (v.x - px);
                if (j) c1 = c; else c0 = c;
            }
        }
    }
    __syncwarp();

    // ---- Phase D: coalesced flush ----
    #pragma unroll
    for (int st = 0; st < 10; ++st) {
        #pragma unroll
        for (int m = 0; m < OUTW / 32; ++m) {
            int t = lane + 32 * m;
            out[(size_t)st * B + base + t] = ob[st * SOUT + t + m];  // SKO(t)=t+m
        }
    }
    // std-dependent streams: wait for the (long since set) flag
    if (lane == 0) while (atomicAdd(&g_flag, 0) == 0) { }
    __syncwarp();
    __threadfence();
    const float stdv = *(volatile float*)&g_obsstd;
    float2* o2 = reinterpret_cast<float2*>(out + 10 * (size_t)B);
    #pragma unroll
    for (int m = 0; m < OUTW / 32; ++m) {
        int t = lane + 32 * m;
        o2[base + t] = make_float2(ob[t + m], stdv);   // h_nout = [h, std]
        out[12 * (size_t)B + base + t] = stdv;         // obs_std
    }
}

// ---------------- launch ----------------
extern "C" void kernel_launch(void* const* d_in, const int* in_sizes, int n_in,
                              void* d_out, int out_size)
{
    const float* x = (const float*)d_in[0];
    const float* y = (const float*)d_in[1];
    float* out = (float*)d_out;
    const int B = in_sizes[0] / 2;   // 262144

    k_init<<<1, 1>>>();
    k_fused<<<NBLK, 32>>>(x, y, out, B,
                          (const float*)d_in[2], (const float*)d_in[3],
                          (const float*)d_in[4], (const float*)d_in[5],
                          (const float*)d_in[6], (const float*)d_in[7],
                          (const float*)d_in[8], (const float*)d_in[9],
                          (const float*)d_in[10], (const float*)d_in[11]);
}

// round 9
// speedup vs baseline: 1.3351x; 1.3351x over previous
#include <cuda_runtime.h>
#include <math.h>

// ---------------- constants (from reference) ----------------
#define SPIN_LEN   100
#define TRAIN_LEN  200000
#define ML_C       2.9086f
#define SL_C       1.898f
#define L2E        1.4426950408889634f

#define CH      8                    // output steps per chain (8 = affine-addr trick)
#define WARM    64                   // discarded convergence steps (multiple of 8)
#define OUTW    (64 * CH)            // 512 output steps per warp (2 chains/thread)
#define NW      (WARM + OUTW)        // 576-step input window per warp
#define SK4(g)  ((g) + ((g) >> 3))   // float4 skew: conflict-free LDS.128 at stride 8
#define SWIN4   (SK4(NW - 1) + 1)    // 647
#define SKO(t)  ((t) + ((t) >> 5))   // float skew for output transpose buffer
#define SOUT    (SKO(OUTW - 1) + 1)  // 527

#define STD_N   (TRAIN_LEN - SPIN_LEN)   // 199900 floats = 49975 float4 exactly
#define STD_N4  (STD_N / 4)              // 49975
#define SB      196                      // 196*256 = 50176 threads >= 49975

// ---------------- device scratch ----------------
__device__ double g_ps[SB];
__device__ double g_pq[SB];
__device__ float  g_obsstd;

__device__ __forceinline__ float ex2f(float x) { float y; asm("ex2.approx.f32 %0, %1;" : "=f"(y) : "f"(x)); return y; }
__device__ __forceinline__ float rcpf(float x) { float y; asm("rcp.approx.f32 %0, %1;" : "=f"(y) : "f"(x)); return y; }

// ---------------- std pass 1: single-wave float4 partial sums ----------------
__global__ void __launch_bounds__(256)
k_std1(const float* __restrict__ y)
{
    __shared__ float ss[8], sq[8];
    const int tid = threadIdx.x;
    const int gi  = blockIdx.x * 256 + tid;

    float a = 0.0f, b = 0.0f;
    if (gi < STD_N4) {
        // y + SPIN_LEN is 16B-aligned (100 floats = 400 bytes)
        float4 v = reinterpret_cast<const float4*>(y + SPIN_LEN)[gi];
        a = ((v.x + v.y) + (v.z + v.w));
        b = fmaf(v.x, v.x, fmaf(v.y, v.y, fmaf(v.z, v.z, v.w * v.w)));
    }
    #pragma unroll
    for (int o = 16; o > 0; o >>= 1) {
        a += __shfl_down_sync(0xffffffffu, a, o);
        b += __shfl_down_sync(0xffffffffu, b, o);
    }
    if ((tid & 31) == 0) { ss[tid >> 5] = a; sq[tid >> 5] = b; }
    __syncthreads();
    if (tid == 0) {
        double sa = 0.0, sb = 0.0;
        #pragma unroll
        for (int w = 0; w < 8; ++w) { sa += (double)ss[w]; sb += (double)sq[w]; }
        g_ps[blockIdx.x] = sa;
        g_pq[blockIdx.x] = sb;
    }
}

// ---------------- std pass 2: final reduce over 196 partials ----------------
__global__ void __launch_bounds__(256)
k_std2()
{
    __shared__ double ss[8], sq[8];
    const int tid = threadIdx.x;
    double a = (tid < SB) ? g_ps[tid] : 0.0;
    double b = (tid < SB) ? g_pq[tid] : 0.0;
    #pragma unroll
    for (int o = 16; o > 0; o >>= 1) {
        a += __shfl_down_sync(0xffffffffu, a, o);
        b += __shfl_down_sync(0xffffffffu, b, o);
    }
    if ((tid & 31) == 0) { ss[tid >> 5] = a; sq[tid >> 5] = b; }
    __syncthreads();
    if (tid == 0) {
        double sa = 0.0, sb = 0.0;
        #pragma unroll
        for (int w = 0; w < 8; ++w) { sa += ss[w]; sb += sq[w]; }
        double n = (double)STD_N;
        double mean = sa / n;
        double var  = (sb - sa * mean) / (n - 1.0);
        g_obsstd = (float)sqrt(var);
    }
}

// ---------------- main chunked-warmup scan ----------------
// 1 warp per block, 512 output steps per warp, 2 chains per thread.
// Inputs (u1,u2) + precomputed ol(u2) staged as float4 in skewed smem;
// outputs transposed through skewed smem, flushed coalesced.
__global__ void __launch_bounds__(32)
k_scan(const float* __restrict__ x, float* __restrict__ out, int B,
       const float* cmean, const float* cstd,
       const float* W_rom, const float* W_rlm, const float* W_rfm,
       const float* b0_yom, const float* W_b1_yom,
       const float* b0_ylm, const float* W_b2_ylm,
       const float* theltaC)
{
    __shared__ float4 sw[SWIN4];
    __shared__ float  ob[10 * SOUT];

    const int lane   = threadIdx.x;
    const int base   = blockIdx.x * OUTW;   // first emitted global step
    const int wstart = base - WARM;         // window start (may be < 0)

    // ---- derived scalar params (cheap, per-block; scalars are L2-hot) ----
    const float eo  = expf(W_rom[0]);
    const float el  = expf(W_rlm[0]);
    const float den = eo + el + expf(W_rfm[0]);
    const float thr = expf(theltaC[0]);
    const float oo1 = eo / den;
    const float ol1 = el / den;
    const float a1  = W_b1_yom[0] / cstd[0];
    const float a1n  = -a1 * L2E;                            // exp(-z)=ex2(fma(c,a1n,k01n))
    const float k01n = -(b0_yom[0] - cmean[0] * a1) * L2E;
    const float a2  = W_b2_ylm[0] / SL_C;
    const float a2n  = -a2 * L2E;
    const float k02n = -(b0_ylm[0] - ML_C * a2) * L2E;

    // ---- stage window (coalesced) + precompute ol(u2) ----
    // Zero-fill for steps < 0 keeps c == 0 exactly (m=min(0,thr)=0, olcc=0, ooc=0).
    #pragma unroll
    for (int g = lane; g < NW; g += 32) {
        int i = wstart + g;
        float u1 = 0.0f, u2 = 0.0f, ol = 0.0f;
        if (i >= 0) {
            float2 v = reinterpret_cast<const float2*>(x)[i];
            u1 = v.x; u2 = v.y;
            ol = ol1 * rcpf(1.0f + ex2f(fmaf(u2, a2n, k02n)));
        }
        sw[SK4(g)] = make_float4(u1, u2, ol, 0.0f);
    }
    __syncwarp();

    const int g0 = lane * CH;           // chain 0 window start (multiple of 8)
    const int g1 = (lane + 32) * CH;    // chain 1 window start
    float c0 = 0.0f, c1 = 0.0f;

    // ---- warmup: 2 interleaved chains, divide-free, affine smem addressing ----
    // step: m = min(u1, thr-c); olcc = min(ol*c, u2); c' = fma(-oo1*c, s, (c-olcc)+m)
    for (int k0 = 0; k0 < WARM; k0 += 8) {
        const float4* p0 = &sw[SK4(g0 + k0)];   // (g+k)>>3 constant over k in [0,8)
        const float4* p1 = &sw[SK4(g1 + k0)];
        #pragma unroll
        for (int k = 0; k < 8; ++k) {
            {
                float4 v = p0[k];
                float s    = rcpf(1.0f + ex2f(fmaf(c0, a1n, k01n)));
                float t    = oo1 * c0;
                float olcc = fminf(v.z * c0, v.y);
                float m    = fminf(v.x, thr - c0);
                c0 = fmaf(-t, s, (c0 - olcc) + m);
            }
            {
                float4 v = p1[k];
                float s    = rcpf(1.0f + ex2f(fmaf(c1, a1n, k01n)));
                float t    = oo1 * c1;
                float olcc = fminf(v.z * c1, v.y);
                float m    = fminf(v.x, thr - c1);
                c1 = fmaf(-t, s, (c1 - olcc) + m);
            }
        }
    }

    // ---- output phase: 8 steps per chain into smem transpose buffer ----
    const int sb0 = 8 * lane + (lane >> 2);                // SKO(8*lane)
    const int sb1 = 8 * (lane + 32) + ((lane + 32) >> 2);  // SKO(8*(lane+32))
    {
        const float4* p0 = &sw[SK4(g0 + WARM)];
        const float4* p1 = &sw[SK4(g1 + WARM)];
        #pragma unroll
        for (int k = 0; k < CH; ++k) {
            #pragma unroll
            for (int j = 0; j < 2; ++j) {
                float  c = j ? c1 : c0;
                float4 v = j ? p1[k] : p0[k];
                float* q = &ob[(j ? sb1 : sb0) + k];

                float s    = rcpf(1.0f + ex2f(fmaf(c, a1n, k01n)));
                float oo   = oo1 * s;
                float ooc  = oo * c;
                float olc  = (c > 0.0f) ? fminf(v.z, v.y * rcpf(c)) : v.z;
                float olcc = olc * c;
                float px   = fmaxf(v.x + c - thr, 0.0f);
                float ib   = (v.x > 0.0f) ? px * rcpf(v.x) : 0.0f;
                float f    = (1.0f - oo) - olc;

                q[0 * SOUT] = ooc + px;   // h_n
                q[1 * SOUT] = c;          // c_n (pre-update)
                q[2 * SOUT] = v.z * c;    // l_n
                q[3 * SOUT] = olcc;       // lc_n
                q[4 * SOUT] = px;         // bp_n
                q[5 * SOUT] = ib;         // g_ib
                q[6 * SOUT] = oo;         // g_oo
                q[7 * SOUT] = v.z;        // g_ol
                q[8 * SOUT] = olc;        // g_olc
                q[9 * SOUT] = f;          // g_f

                c = ((c - ooc) - olcc) + (v.x - px);
                if (j) c1 = c; else c0 = c;
            }
        }
    }
    __syncwarp();

    // ---- coalesced flush (also produces h_nout and obs_std streams) ----
    #pragma unroll
    for (int st = 0; st < 10; ++st) {
        #pragma unroll
        for (int m = 0; m < OUTW / 32; ++m) {
            int t = lane + 32 * m;
            out[(size_t)st * B + base + t] = ob[st * SOUT + t + m];  // SKO(t)=t+m
        }
    }
    const float stdv = g_obsstd;
    float2* o2 = reinterpret_cast<float2*>(out + 10 * (size_t)B);
    #pragma unroll
    for (int m = 0; m < OUTW / 32; ++m) {
        int t = lane + 32 * m;
        o2[base + t] = make_float2(ob[t + m], stdv);   // h_nout = [h, std]
        out[12 * (size_t)B + base + t] = stdv;         // obs_std
    }
}

// ---------------- launch ----------------
extern "C" void kernel_launch(void* const* d_in, const int* in_sizes, int n_in,
                              void* d_out, int out_size)
{
    const float* x = (const float*)d_in[0];
    const float* y = (const float*)d_in[1];
    float* out = (float*)d_out;
    const int B = in_sizes[0] / 2;   // 262144

    k_std1<<<SB, 256>>>(y);
    k_std2<<<1, 256>>>();

    const int blocks = B / OUTW;     // 512 one-warp blocks
    k_scan<<<blocks, 32>>>(x, out, B,
                           (const float*)d_in[2], (const float*)d_in[3],
                           (const float*)d_in[4], (const float*)d_in[5],
                           (const float*)d_in[6], (const float*)d_in[7],
                           (const float*)d_in[8], (const float*)d_in[9],
                           (const float*)d_in[10], (const float*)d_in[11]);
}

// round 10
// speedup vs baseline: 1.7089x; 1.2800x over previous
#include <cuda_runtime.h>
#include <math.h>

// ---------------- constants (from reference) ----------------
#define SPIN_LEN   100
#define TRAIN_LEN  200000
#define ML_C       2.9086f
#define SL_C       1.898f
#define L2E        1.4426950408889634f

#define CH      8                    // output steps per chain (8 = affine-addr trick)
#define WARM    48                   // discarded convergence steps (multiple of 8)
#define OUTW    (32 * CH)            // 256 output steps per warp (1 chain/thread)
#define NW      (WARM + OUTW)        // 304-step input window per warp
#define SK4(g)  ((g) + ((g) >> 3))   // float4 skew: conflict-free LDS.128 at stride 8
#define SWIN4   (SK4(NW - 1) + 1)    // 341
#define SKO(t)  ((t) + ((t) >> 5))   // float skew for output transpose buffer
#define SOUT    (SKO(OUTW - 1) + 1)  // 263

#define STD_N   (TRAIN_LEN - SPIN_LEN)   // 199900 floats = 49975 float4 exactly
#define STD_N4  (STD_N / 4)              // 49975
#define SB      196                      // 196*256 = 50176 threads >= 49975

// ---------------- device scratch ----------------
__device__ double g_ps[SB];
__device__ double g_pq[SB];

__device__ __forceinline__ float ex2f(float x) { float y; asm("ex2.approx.f32 %0, %1;" : "=f"(y) : "f"(x)); return y; }
__device__ __forceinline__ float rcpf(float x) { float y; asm("rcp.approx.f32 %0, %1;" : "=f"(y) : "f"(x)); return y; }

// ---------------- std pass 1: single-wave float4 partial sums ----------------
__global__ void __launch_bounds__(256)
k_std1(const float* __restrict__ y)
{
    __shared__ float ss[8], sq[8];
    const int tid = threadIdx.x;
    const int gi  = blockIdx.x * 256 + tid;

    float a = 0.0f, b = 0.0f;
    if (gi < STD_N4) {
        // y + SPIN_LEN is 16B-aligned (100 floats = 400 bytes)
        float4 v = reinterpret_cast<const float4*>(y + SPIN_LEN)[gi];
        a = ((v.x + v.y) + (v.z + v.w));
        b = fmaf(v.x, v.x, fmaf(v.y, v.y, fmaf(v.z, v.z, v.w * v.w)));
    }
    #pragma unroll
    for (int o = 16; o > 0; o >>= 1) {
        a += __shfl_down_sync(0xffffffffu, a, o);
        b += __shfl_down_sync(0xffffffffu, b, o);
    }
    if ((tid & 31) == 0) { ss[tid >> 5] = a; sq[tid >> 5] = b; }
    __syncthreads();
    if (tid == 0) {
        double sa = 0.0, sb = 0.0;
        #pragma unroll
        for (int w = 0; w < 8; ++w) { sa += (double)ss[w]; sb += (double)sq[w]; }
        g_ps[blockIdx.x] = sa;
        g_pq[blockIdx.x] = sb;
    }
}

// ---------------- main chunked-warmup scan ----------------
// 1024 one-warp blocks, 256 output steps per warp, 1 chain per thread
// (WARM=48 discarded + CH=8 emitted). Each block also redundantly reduces the
// 196 std partials (L2-hot, deterministic fixed order) -> no k_std2 launch.
__global__ void __launch_bounds__(32)
k_scan(const float* __restrict__ x, float* __restrict__ out, int B,
       const float* cmean, const float* cstd,
       const float* W_rom, const float* W_rlm, const float* W_rfm,
       const float* b0_yom, const float* W_b1_yom,
       const float* b0_ylm, const float* W_b2_ylm,
       const float* theltaC)
{
    __shared__ float4 sw[SWIN4];
    __shared__ float  ob[10 * SOUT];

    const int lane   = threadIdx.x;
    const int base   = blockIdx.x * OUTW;   // first emitted global step
    const int wstart = base - WARM;         // window start (may be < 0)

    // ---- std final reduce (redundant per block; 196 doubles from L2) ----
    double sa = 0.0, sb = 0.0;
    #pragma unroll
    for (int i = lane; i < SB; i += 32) { sa += g_ps[i]; sb += g_pq[i]; }
    #pragma unroll
    for (int o = 16; o > 0; o >>= 1) {
        sa += __shfl_down_sync(0xffffffffu, sa, o);
        sb += __shfl_down_sync(0xffffffffu, sb, o);
    }
    float stdv;
    if (lane == 0) {
        double n    = (double)STD_N;
        double mean = sa / n;
        double var  = (sb - sa * mean) / (n - 1.0);
        stdv = (float)sqrt(var);
    }
    stdv = __shfl_sync(0xffffffffu, stdv, 0);

    // ---- derived scalar params (cheap, per-block; scalars are L2-hot) ----
    const float eo  = expf(W_rom[0]);
    const float el  = expf(W_rlm[0]);
    const float den = eo + el + expf(W_rfm[0]);
    const float thr = expf(theltaC[0]);
    const float oo1 = eo / den;
    const float ol1 = el / den;
    const float a1  = W_b1_yom[0] / cstd[0];
    const float a1n  = -a1 * L2E;                            // exp(-z)=ex2(fma(c,a1n,k01n))
    const float k01n = -(b0_yom[0] - cmean[0] * a1) * L2E;
    const float a2  = W_b2_ylm[0] / SL_C;
    const float a2n  = -a2 * L2E;
    const float k02n = -(b0_ylm[0] - ML_C * a2) * L2E;

    // ---- stage window (coalesced) + precompute ol(u2) ----
    // Zero-fill for steps < 0 keeps c == 0 exactly (m=min(0,thr)=0, olcc=0, ooc=0).
    #pragma unroll
    for (int g = lane; g < NW; g += 32) {
        int i = wstart + g;
        float u1 = 0.0f, u2 = 0.0f, ol = 0.0f;
        if (i >= 0) {
            float2 v = reinterpret_cast<const float2*>(x)[i];
            u1 = v.x; u2 = v.y;
            ol = ol1 * rcpf(1.0f + ex2f(fmaf(u2, a2n, k02n)));
        }
        sw[SK4(g)] = make_float4(u1, u2, ol, 0.0f);
    }
    __syncwarp();

    const int g0 = lane * CH;          // chain window start (multiple of 8)
    float c = 0.0f;

    // ---- warmup: divide-free, affine smem addressing ----
    // step: m = min(u1, thr-c); olcc = min(ol*c, u2); c' = fma(-oo1*c, s, (c-olcc)+m)
    for (int k0 = 0; k0 < WARM; k0 += 8) {
        const float4* p = &sw[SK4(g0 + k0)];   // (g+k)>>3 constant over k in [0,8)
        #pragma unroll
        for (int k = 0; k < 8; ++k) {
            float4 v = p[k];
            float s    = rcpf(1.0f + ex2f(fmaf(c, a1n, k01n)));
            float t    = oo1 * c;
            float olcc = fminf(v.z * c, v.y);
            float m    = fminf(v.x, thr - c);
            c = fmaf(-t, s, (c - olcc) + m);
        }
    }

    // ---- output phase: 8 steps into smem transpose buffer ----
    const int sb0 = 8 * lane + (lane >> 2);    // SKO(8*lane), k-invariant base
    {
        const float4* p = &sw[SK4(g0 + WARM)];
        #pragma unroll
        for (int k = 0; k < CH; ++k) {
            float4 v = p[k];
            float* q = &ob[sb0 + k];

            float s    = rcpf(1.0f + ex2f(fmaf(c, a1n, k01n)));
            float oo   = oo1 * s;
            float ooc  = oo * c;
            float olc  = (c > 0.0f) ? fminf(v.z, v.y * rcpf(c)) : v.z;
            float olcc = olc * c;
            float px   = fmaxf(v.x + c - thr, 0.0f);
            float ib   = (v.x > 0.0f) ? px * rcpf(v.x) : 0.0f;
            float f    = (1.0f - oo) - olc;

            q[0 * SOUT] = ooc + px;   // h_n
            q[1 * SOUT] = c;          // c_n (pre-update)
            q[2 * SOUT] = v.z * c;    // l_n
            q[3 * SOUT] = olcc;       // lc_n
            q[4 * SOUT] = px;         // bp_n
            q[5 * SOUT] = ib;         // g_ib
            q[6 * SOUT] = oo;         // g_oo
            q[7 * SOUT] = v.z;        // g_ol
            q[8 * SOUT] = olc;        // g_olc
            q[9 * SOUT] = f;          // g_f

            c = ((c - ooc) - olcc) + (v.x - px);
        }
    }
    __syncwarp();

    // ---- coalesced flush (also produces h_nout and obs_std streams) ----
    #pragma unroll
    for (int st = 0; st < 10; ++st) {
        #pragma unroll
        for (int m = 0; m < OUTW / 32; ++m) {
            int t = lane + 32 * m;
            out[(size_t)st * B + base + t] = ob[st * SOUT + t + m];  // SKO(t)=t+m
        }
    }
    float2* o2 = reinterpret_cast<float2*>(out + 10 * (size_t)B);
    #pragma unroll
    for (int m = 0; m < OUTW / 32; ++m) {
        int t = lane + 32 * m;
        o2[base + t] = make_float2(ob[t + m], stdv);   // h_nout = [h, std]
        out[12 * (size_t)B + base + t] = stdv;         // obs_std
    }
}

// ---------------- launch ----------------
extern "C" void kernel_launch(void* const* d_in, const int* in_sizes, int n_in,
                              void* d_out, int out_size)
{
    const float* x = (const float*)d_in[0];
    const float* y = (const float*)d_in[1];
    float* out = (float*)d_out;
    const int B = in_sizes[0] / 2;   // 262144

    k_std1<<<SB, 256>>>(y);

    const int blocks = B / OUTW;     // 1024 one-warp blocks
    k_scan<<<blocks, 32>>>(x, out, B,
                           (const float*)d_in[2], (const float*)d_in[3],
                           (const float*)d_in[4], (const float*)d_in[5],
                           (const float*)d_in[6], (const float*)d_in[7],
                           (const float*)d_in[8], (const float*)d_in[9],
                           (const float*)d_in[10], (const float*)d_in[11]);
}

// round 11
// speedup vs baseline: 1.8665x; 1.0922x over previous
#include <cuda_runtime.h>
#include <math.h>

// ---------------- constants (from reference) ----------------
#define SPIN_LEN   100
#define TRAIN_LEN  200000
#define ML_C       2.9086f
#define SL_C       1.898f
#define L2E        1.4426950408889634f

#define CH      4                    // output steps per chain
#define WARM    32                   // discarded convergence steps (multiple of 8)
#define OUTW    (32 * CH)            // 128 output steps per warp (1 chain/thread)
#define NW      (WARM + OUTW)        // 160-step input window per warp
#define SK4(g)  ((g) + ((g) >> 3))   // float4 skew: conflict-free LDS.128 at stride 4/8
#define SWIN4   (SK4(NW - 1) + 1)    // 179
#define SKO(t)  ((t) + ((t) >> 5))   // float skew for output transpose buffer
#define SOUT    (SKO(OUTW - 1) + 1)  // 131

#define STD_N   (TRAIN_LEN - SPIN_LEN)   // 199900 floats = 49975 float4 exactly
#define STD_N4  (STD_N / 4)              // 49975
#define SB      196                      // 196*256 = 50176 threads >= 49975

// ---------------- device scratch ----------------
__device__ float g_ps[SB];
__device__ float g_pq[SB];

__device__ __forceinline__ float ex2f(float x) { float y; asm("ex2.approx.f32 %0, %1;" : "=f"(y) : "f"(x)); return y; }
__device__ __forceinline__ float rcpf(float x) { float y; asm("rcp.approx.f32 %0, %1;" : "=f"(y) : "f"(x)); return y; }

// ---------------- std pass 1: single-wave float4 partial sums ----------------
__global__ void __launch_bounds__(256)
k_std1(const float* __restrict__ y)
{
    __shared__ float ss[8], sq[8];
    const int tid = threadIdx.x;
    const int gi  = blockIdx.x * 256 + tid;

    float a = 0.0f, b = 0.0f;
    if (gi < STD_N4) {
        // y + SPIN_LEN is 16B-aligned (100 floats = 400 bytes)
        float4 v = reinterpret_cast<const float4*>(y + SPIN_LEN)[gi];
        a = ((v.x + v.y) + (v.z + v.w));
        b = fmaf(v.x, v.x, fmaf(v.y, v.y, fmaf(v.z, v.z, v.w * v.w)));
    }
    #pragma unroll
    for (int o = 16; o > 0; o >>= 1) {
        a += __shfl_down_sync(0xffffffffu, a, o);
        b += __shfl_down_sync(0xffffffffu, b, o);
    }
    if ((tid & 31) == 0) { ss[tid >> 5] = a; sq[tid >> 5] = b; }
    __syncthreads();
    if (tid == 0) {
        float sa = 0.0f, sb = 0.0f;
        #pragma unroll
        for (int w = 0; w < 8; ++w) { sa += ss[w]; sb += sq[w]; }
        g_ps[blockIdx.x] = sa;
        g_pq[blockIdx.x] = sb;
    }
}

// ---------------- main chunked-warmup scan ----------------
// 2048 one-warp blocks (all co-resident: ~8KB smem each), 128 output steps per
// warp, 1 chain per thread: WARM=32 discarded + CH=4 emitted = 36 serial steps.
// Each block redundantly reduces the 196 fp32 std partials (L2-hot, fixed
// order -> deterministic, identical across blocks). No second std kernel.
__global__ void __launch_bounds__(32)
k_scan(const float* __restrict__ x, float* __restrict__ out, int B,
       const float* cmean, const float* cstd,
       const float* W_rom, const float* W_rlm, const float* W_rfm,
       const float* b0_yom, const float* W_b1_yom,
       const float* b0_ylm, const float* W_b2_ylm,
       const float* theltaC)
{
    __shared__ float4 sw[SWIN4];
    __shared__ float  ob[10 * SOUT];

    const int lane   = threadIdx.x;
    const int base   = blockIdx.x * OUTW;   // first emitted global step
    const int wstart = base - WARM;         // window start (may be < 0)

    // ---- std final reduce (fp32, fixed order, redundant per block) ----
    float sa = 0.0f, sb = 0.0f;
    #pragma unroll
    for (int i = lane; i < SB; i += 32) { sa += g_ps[i]; sb += g_pq[i]; }
    #pragma unroll
    for (int o = 16; o > 0; o >>= 1) {
        sa += __shfl_down_sync(0xffffffffu, sa, o);
        sb += __shfl_down_sync(0xffffffffu, sb, o);
    }
    float stdv;
    if (lane == 0) {
        const float n = (float)STD_N;
        float mean = sa / n;
        float var  = (sb - sa * mean) / (n - 1.0f);
        stdv = sqrtf(var);
    }
    stdv = __shfl_sync(0xffffffffu, stdv, 0);

    // ---- derived scalar params (cheap, per-block; scalars are L2-hot) ----
    const float eo  = expf(W_rom[0]);
    const float el  = expf(W_rlm[0]);
    const float den = eo + el + expf(W_rfm[0]);
    const float thr = expf(theltaC[0]);
    const float oo1 = eo / den;
    const float ol1 = el / den;
    const float a1  = W_b1_yom[0] / cstd[0];
    const float a1n  = -a1 * L2E;                            // exp(-z)=ex2(fma(c,a1n,k01n))
    const float k01n = -(b0_yom[0] - cmean[0] * a1) * L2E;
    const float a2  = W_b2_ylm[0] / SL_C;
    const float a2n  = -a2 * L2E;
    const float k02n = -(b0_ylm[0] - ML_C * a2) * L2E;

    // ---- stage window (coalesced) + precompute ol(u2) ----
    // Zero-fill for steps < 0 keeps c == 0 exactly (m=min(0,thr)=0, olcc=0, ooc=0).
    #pragma unroll
    for (int g = lane; g < NW; g += 32) {
        int i = wstart + g;
        float u1 = 0.0f, u2 = 0.0f, ol = 0.0f;
        if (i >= 0) {
            float2 v = reinterpret_cast<const float2*>(x)[i];
            u1 = v.x; u2 = v.y;
            ol = ol1 * rcpf(1.0f + ex2f(fmaf(u2, a2n, k02n)));
        }
        sw[SK4(g)] = make_float4(u1, u2, ol, 0.0f);
    }
    __syncwarp();

    const int g0 = lane * CH;          // chain window start (multiple of 4)
    float c = 0.0f;

    // ---- warmup: divide-free, affine smem addressing ----
    // A 4-aligned 4-step range never crosses an 8-boundary, so (g)>>3 is
    // constant over k in [0,4) -> base pointer per 4 steps, immediate offsets.
    // step: m = min(u1, thr-c); olcc = min(ol*c, u2); c' = fma(-oo1*c, s, (c-olcc)+m)
    for (int k0 = 0; k0 < WARM; k0 += 4) {
        const float4* p = &sw[SK4(g0 + k0)];
        #pragma unroll
        for (int k = 0; k < 4; ++k) {
            float4 v = p[k];
            float s    = rcpf(1.0f + ex2f(fmaf(c, a1n, k01n)));
            float t    = oo1 * c;
            float olcc = fminf(v.z * c, v.y);
            float m    = fminf(v.x, thr - c);
            c = fmaf(-t, s, (c - olcc) + m);
        }
    }

    // ---- output phase: 4 steps into smem transpose buffer ----
    // (4*lane+k)>>5 = lane>>3 is k-invariant -> affine store base.
    const int sb0 = CH * lane + (lane >> 3);   // SKO(4*lane)
    {
        const float4* p = &sw[SK4(g0 + WARM)];
        #pragma unroll
        for (int k = 0; k < CH; ++k) {
            float4 v = p[k];
            float* q = &ob[sb0 + k];

            float s    = rcpf(1.0f + ex2f(fmaf(c, a1n, k01n)));
            float oo   = oo1 * s;
            float ooc  = oo * c;
            float olc  = (c > 0.0f) ? fminf(v.z, v.y * rcpf(c)) : v.z;
            float olcc = olc * c;
            float px   = fmaxf(v.x + c - thr, 0.0f);
            float ib   = (v.x > 0.0f) ? px * rcpf(v.x) : 0.0f;
            float f    = (1.0f - oo) - olc;

            q[0 * SOUT] = ooc + px;   // h_n
            q[1 * SOUT] = c;          // c_n (pre-update)
            q[2 * SOUT] = v.z * c;    // l_n
            q[3 * SOUT] = olcc;       // lc_n
            q[4 * SOUT] = px;         // bp_n
            q[5 * SOUT] = ib;         // g_ib
            q[6 * SOUT] = oo;         // g_oo
            q[7 * SOUT] = v.z;        // g_ol
            q[8 * SOUT] = olc;        // g_olc
            q[9 * SOUT] = f;          // g_f

            c = ((c - ooc) - olcc) + (v.x - px);
        }
    }
    __syncwarp();

    // ---- coalesced flush (also produces h_nout and obs_std streams) ----
    #pragma unroll
    for (int st = 0; st < 10; ++st) {
        #pragma unroll
        for (int m = 0; m < OUTW / 32; ++m) {
            int t = lane + 32 * m;
            out[(size_t)st * B + base + t] = ob[st * SOUT + t + m];  // SKO(t)=t+m
        }
    }
    float2* o2 = reinterpret_cast<float2*>(out + 10 * (size_t)B);
    #pragma unroll
    for (int m = 0; m < OUTW / 32; ++m) {
        int t = lane + 32 * m;
        o2[base + t] = make_float2(ob[t + m], stdv);   // h_nout = [h, std]
        out[12 * (size_t)B + base + t] = stdv;         // obs_std
    }
}

// ---------------- launch ----------------
extern "C" void kernel_launch(void* const* d_in, const int* in_sizes, int n_in,
                              void* d_out, int out_size)
{
    const float* x = (const float*)d_in[0];
    const float* y = (const float*)d_in[1];
    float* out = (float*)d_out;
    const int B = in_sizes[0] / 2;   // 262144

    k_std1<<<SB, 256>>>(y);

    const int blocks = B / OUTW;     // 2048 one-warp blocks
    k_scan<<<blocks, 32>>>(x, out, B,
                           (const float*)d_in[2], (const float*)d_in[3],
                           (const float*)d_in[4], (const float*)d_in[5],
                           (const float*)d_in[6], (const float*)d_in[7],
                           (const float*)d_in[8], (const float*)d_in[9],
                           (const float*)d_in[10], (const float*)d_in[11]);
}